// round 2
// baseline (speedup 1.0000x reference)
#include <cuda_runtime.h>
#include <cstdint>

// out[n,64] = sum over edges e with dst[e]==n of x[src[e],:] * w[e]
// Inputs (metadata order): x (float32, N*64), edge_index (int64-or-int32, 2*E), edge_weight (float32, E)

static constexpr int D = 64;               // feature dim
static constexpr int LANES_PER_EDGE = 16;  // 16 threads * float4 = 64 floats

// Probe result: 1 if edge_index is stored as int64, 0 if int32.
__device__ int g_idx_is64;

// If edge_index is little-endian int64 (values in [0,1e5)), every odd 32-bit
// word is zero. If int32, odd words are random node ids — all-zero over 1024
// samples has probability ~1e-5024. Deterministic: same input -> same flag.
__global__ void probe_idx_dtype_kernel(const int* __restrict__ ei32, int E) {
    __shared__ int any_nonzero;
    if (threadIdx.x == 0) any_nonzero = 0;
    __syncthreads();
    int n = E < 1024 ? E : 1024;
    for (int i = threadIdx.x; i < n; i += blockDim.x) {
        if (ei32[2 * i + 1] != 0) any_nonzero = 1;
    }
    __syncthreads();
    if (threadIdx.x == 0) g_idx_is64 = (any_nonzero == 0) ? 1 : 0;
}

__global__ void zero_out_kernel(float4* __restrict__ out, int n4) {
    int i = blockIdx.x * blockDim.x + threadIdx.x;
    if (i < n4) out[i] = make_float4(0.f, 0.f, 0.f, 0.f);
}

__global__ __launch_bounds__(256)
void mp_scatter_kernel(const float* __restrict__ x,
                       const void* __restrict__ edge_index,
                       const float* __restrict__ w,
                       float* __restrict__ out,
                       int E) {
    int gid  = blockIdx.x * blockDim.x + threadIdx.x;
    int e    = gid >> 4;        // edge id
    int lane = gid & 15;        // which float4 of the 64-dim row
    if (e >= E) return;

    const int is64 = g_idx_is64;   // uniform branch, cached in L1/const path

    long long s, d;
    if (is64) {
        const long long* ei = (const long long*)edge_index;
        s = __ldg(&ei[e]);
        d = __ldg(&ei[E + e]);
    } else {
        const int* ei = (const int*)edge_index;
        s = (long long)__ldg(&ei[e]);
        d = (long long)__ldg(&ei[E + e]);
    }
    float wt = __ldg(&w[e]);

    const float4 xv = *reinterpret_cast<const float4*>(x + s * D + lane * 4);
    float4 m;
    m.x = xv.x * wt;
    m.y = xv.y * wt;
    m.z = xv.z * wt;
    m.w = xv.w * wt;

    float* p = out + d * D + lane * 4;
    // Vectorized fire-and-forget global reduction (sm_90+): one 16B atomic add.
    asm volatile("red.global.add.v4.f32 [%0], {%1, %2, %3, %4};"
                 :: "l"(p), "f"(m.x), "f"(m.y), "f"(m.z), "f"(m.w)
                 : "memory");
}

extern "C" void kernel_launch(void* const* d_in, const int* in_sizes, int n_in,
                              void* d_out, int out_size) {
    const float* x   = (const float*)d_in[0];
    const void*  ei  = d_in[1];
    const float* w   = (const float*)d_in[2];
    float*       out = (float*)d_out;

    const int E = in_sizes[1] / 2;   // edge_index is (2, E)

    // 0) probe index dtype (1 block, ~2us)
    probe_idx_dtype_kernel<<<1, 256>>>((const int*)ei, E);

    // 1) zero the output (harness poisons it to 0xAA)
    {
        int n4 = out_size / 4;
        int threads = 256;
        int blocks = (n4 + threads - 1) / threads;
        zero_out_kernel<<<blocks, threads>>>((float4*)out, n4);
    }

    // 2) gather-multiply-scatter
    {
        long long total = (long long)E * LANES_PER_EDGE;
        int threads = 256;
        int blocks = (int)((total + threads - 1) / threads);
        mp_scatter_kernel<<<blocks, threads>>>(x, ei, w, out, E);
    }
}

// round 3
// speedup vs baseline: 1.0304x; 1.0304x over previous
#include <cuda_runtime.h>
#include <cstdint>

// out[n,64] = sum over edges e with dst[e]==n of x[src[e],:] * w[e]
// Inputs (metadata order): x (float32, N*64), edge_index (int64-or-int32, 2*E), edge_weight (float32, E)

static constexpr int D = 64;               // feature dim
static constexpr int LANES_PER_EDGE = 16;  // 16 threads * float4 = 64 floats

// Probe result: 1 if edge_index is stored as int64, 0 if int32.
__device__ int g_idx_is64;

// Fused: zero the output AND (block 0 only) probe the index dtype.
// If edge_index is little-endian int64 with values < 2^31, every odd 32-bit
// word is zero. If int32, odd words are random node ids; all-zero over 1024
// samples has probability ~1e-5024. Deterministic.
__global__ void zero_and_probe_kernel(float4* __restrict__ out, int n4,
                                      const int* __restrict__ ei32, int E) {
    if (blockIdx.x == 0) {
        __shared__ int any_nonzero;
        if (threadIdx.x == 0) any_nonzero = 0;
        __syncthreads();
        int n = E < 1024 ? E : 1024;
        for (int i = threadIdx.x; i < n; i += blockDim.x) {
            if (ei32[2 * i + 1] != 0) any_nonzero = 1;
        }
        __syncthreads();
        if (threadIdx.x == 0) g_idx_is64 = (any_nonzero == 0) ? 1 : 0;
    }
    int i = blockIdx.x * blockDim.x + threadIdx.x;
    if (i < n4) out[i] = make_float4(0.f, 0.f, 0.f, 0.f);
}

__global__ __launch_bounds__(256)
void mp_scatter_kernel(const float* __restrict__ x,
                       const void* __restrict__ edge_index,
                       const float* __restrict__ w,
                       float* __restrict__ out,
                       int E) {
    int gid  = blockIdx.x * blockDim.x + threadIdx.x;
    int e    = gid >> 4;        // edge id
    int lane = gid & 15;        // which float4 of the 64-dim row
    if (e >= E) return;

    const int is64 = g_idx_is64;   // uniform branch

    int s, d;
    if (is64) {
        const long long* ei = (const long long*)edge_index;
        s = (int)__ldg(&ei[e]);
        d = (int)__ldg(&ei[E + e]);
    } else {
        const int* ei = (const int*)edge_index;
        s = __ldg(&ei[e]);
        d = __ldg(&ei[E + e]);
    }
    float wt = __ldg(&w[e]);

    const float4 xv = __ldg(reinterpret_cast<const float4*>(
        x + (long long)s * D + lane * 4));
    float4 m;
    m.x = xv.x * wt;
    m.y = xv.y * wt;
    m.z = xv.z * wt;
    m.w = xv.w * wt;

    float* p = out + (long long)d * D + lane * 4;
    // Vectorized fire-and-forget global reduction (sm_90+): one 16B atomic add.
    asm volatile("red.global.add.v4.f32 [%0], {%1, %2, %3, %4};"
                 :: "l"(p), "f"(m.x), "f"(m.y), "f"(m.z), "f"(m.w)
                 : "memory");
}

extern "C" void kernel_launch(void* const* d_in, const int* in_sizes, int n_in,
                              void* d_out, int out_size) {
    const float* x   = (const float*)d_in[0];
    const void*  ei  = d_in[1];
    const float* w   = (const float*)d_in[2];
    float*       out = (float*)d_out;

    const int E = in_sizes[1] / 2;   // edge_index is (2, E)

    // 1) zero output (poisoned 0xAA by harness) + probe index dtype (block 0)
    {
        int n4 = out_size / 4;
        int threads = 256;
        int blocks = (n4 + threads - 1) / threads;
        zero_and_probe_kernel<<<blocks, threads>>>((float4*)out, n4,
                                                   (const int*)ei, E);
    }

    // 2) gather-multiply-scatter
    {
        long long total = (long long)E * LANES_PER_EDGE;
        int threads = 256;
        int blocks = (int)((total + threads - 1) / threads);
        mp_scatter_kernel<<<blocks, threads>>>(x, ei, w, out, E);
    }
}

// round 4
// speedup vs baseline: 1.0638x; 1.0324x over previous
#include <cuda_runtime.h>
#include <cstdint>

// out[n,64] = sum over edges e with dst[e]==n of x[src[e],:] * w[e]
// Inputs (metadata order): x (float32, N*64), edge_index (int64-or-int32, 2*E), edge_weight (float32, E)

static constexpr int D = 64;               // feature dim

// Probe result: 1 if edge_index is stored as int64, 0 if int32.
__device__ int g_idx_is64;

// Fused: zero the output AND (block 0 only) probe the index dtype.
// If edge_index is little-endian int64 with values < 2^31, every odd 32-bit
// word is zero. If int32, odd words are random node ids; all-zero over 1024
// samples has probability ~1e-5024. Deterministic.
__global__ void zero_and_probe_kernel(float4* __restrict__ out, int n4,
                                      const int* __restrict__ ei32, int E) {
    if (blockIdx.x == 0) {
        __shared__ int any_nonzero;
        if (threadIdx.x == 0) any_nonzero = 0;
        __syncthreads();
        int n = E < 1024 ? E : 1024;
        for (int i = threadIdx.x; i < n; i += blockDim.x) {
            if (ei32[2 * i + 1] != 0) any_nonzero = 1;
        }
        __syncthreads();
        if (threadIdx.x == 0) g_idx_is64 = (any_nonzero == 0) ? 1 : 0;
    }
    int i = blockIdx.x * blockDim.x + threadIdx.x;
    if (i < n4) out[i] = make_float4(0.f, 0.f, 0.f, 0.f);
}

// Two independent edges per thread (e and e+Eh) -> 2 gathers in flight,
// hiding L2 latency (~250 cyc) behind doubled MLP.
__global__ __launch_bounds__(256)
void mp_scatter2_kernel(const float* __restrict__ x,
                        const void* __restrict__ edge_index,
                        const float* __restrict__ w,
                        float* __restrict__ out,
                        int E, int Eh) {
    int gid  = blockIdx.x * blockDim.x + threadIdx.x;
    int e    = gid >> 4;        // first edge id
    int lane = gid & 15;        // which float4 of the 64-dim row
    if (e >= Eh) return;

    int e2 = e + Eh;
    bool has2 = (e2 < E);

    const int is64 = g_idx_is64;   // uniform branch

    int s0, d0, s1 = 0, d1 = 0;
    if (is64) {
        const long long* p = (const long long*)edge_index;
        s0 = (int)__ldg(p + e);
        d0 = (int)__ldg(p + E + e);
        if (has2) {
            s1 = (int)__ldg(p + e2);
            d1 = (int)__ldg(p + E + e2);
        }
    } else {
        const int* p = (const int*)edge_index;
        s0 = __ldg(p + e);
        d0 = __ldg(p + E + e);
        if (has2) {
            s1 = __ldg(p + e2);
            d1 = __ldg(p + E + e2);
        }
    }
    float w0 = __ldg(w + e);
    float w1 = has2 ? __ldg(w + e2) : 0.f;

    // Issue BOTH gathers before any RED (the volatile asm fences loads).
    const float4 a = __ldg(reinterpret_cast<const float4*>(
        x + (long long)s0 * D + lane * 4));
    float4 b = make_float4(0.f, 0.f, 0.f, 0.f);
    if (has2) {
        b = __ldg(reinterpret_cast<const float4*>(
            x + (long long)s1 * D + lane * 4));
    }

    float4 m0, m1;
    m0.x = a.x * w0; m0.y = a.y * w0; m0.z = a.z * w0; m0.w = a.w * w0;
    m1.x = b.x * w1; m1.y = b.y * w1; m1.z = b.z * w1; m1.w = b.w * w1;

    float* p0 = out + (long long)d0 * D + lane * 4;
    asm volatile("red.global.add.v4.f32 [%0], {%1, %2, %3, %4};"
                 :: "l"(p0), "f"(m0.x), "f"(m0.y), "f"(m0.z), "f"(m0.w)
                 : "memory");
    if (has2) {
        float* p1 = out + (long long)d1 * D + lane * 4;
        asm volatile("red.global.add.v4.f32 [%0], {%1, %2, %3, %4};"
                     :: "l"(p1), "f"(m1.x), "f"(m1.y), "f"(m1.z), "f"(m1.w)
                     : "memory");
    }
}

extern "C" void kernel_launch(void* const* d_in, const int* in_sizes, int n_in,
                              void* d_out, int out_size) {
    const float* x   = (const float*)d_in[0];
    const void*  ei  = d_in[1];
    const float* w   = (const float*)d_in[2];
    float*       out = (float*)d_out;

    const int E  = in_sizes[1] / 2;   // edge_index is (2, E)
    const int Eh = (E + 1) / 2;       // edges handled in the first slot

    // 1) zero output (poisoned 0xAA by harness) + probe index dtype (block 0)
    {
        int n4 = out_size / 4;
        int threads = 256;
        int blocks = (n4 + threads - 1) / threads;
        zero_and_probe_kernel<<<blocks, threads>>>((float4*)out, n4,
                                                   (const int*)ei, E);
    }

    // 2) gather-multiply-scatter, 2 edges per thread
    {
        long long total = (long long)Eh * 16;
        int threads = 256;
        int blocks = (int)((total + threads - 1) / threads);
        mp_scatter2_kernel<<<blocks, threads>>>(x, ei, w, out, E, Eh);
    }
}

// round 5
// speedup vs baseline: 1.1411x; 1.0727x over previous
#include <cuda_runtime.h>
#include <cstdint>

// out[n,64] = sum over edges e with dst[e]==n of x[src[e],:] * w[e]
// Inputs: x (float32, N*64), edge_index ((2,E), int64-or-int32), edge_weight (float32, E)

static constexpr int D       = 64;   // feature dim
static constexpr int TPB     = 256;  // threads per block
static constexpr int BATCH   = 256;  // edges staged per block iteration
static constexpr int GROUPS  = TPB / 16;      // 16 edge-groups per pass
static constexpr int PASSES  = BATCH / GROUPS; // 16 serial edges per thread
static constexpr int UNROLL  = 4;    // gathers in flight per thread

// Probe result: 1 if edge_index is stored as int64, 0 if int32.
__device__ int g_idx_is64;

// Fused: zero the output AND (block 0 only) probe the index dtype.
// int64 indices < 2^31 => every odd 32-bit word is zero; int32 indices are
// random node ids, so all-zero over 1024 samples has probability ~1e-5024.
__global__ void zero_and_probe_kernel(float4* __restrict__ out, int n4,
                                      const int* __restrict__ ei32, int E) {
    if (blockIdx.x == 0) {
        __shared__ int any_nonzero;
        if (threadIdx.x == 0) any_nonzero = 0;
        __syncthreads();
        int n = E < 1024 ? E : 1024;
        for (int i = threadIdx.x; i < n; i += blockDim.x)
            if (ei32[2 * i + 1] != 0) any_nonzero = 1;
        __syncthreads();
        if (threadIdx.x == 0) g_idx_is64 = (any_nonzero == 0) ? 1 : 0;
    }
    int i = blockIdx.x * blockDim.x + threadIdx.x;
    if (i < n4) out[i] = make_float4(0.f, 0.f, 0.f, 0.f);
}

__global__ __launch_bounds__(TPB)
void mp_scatter_batched_kernel(const float* __restrict__ x,
                               const void* __restrict__ edge_index,
                               const float* __restrict__ w,
                               float* __restrict__ out,
                               int E) {
    __shared__ int   s_src[BATCH];
    __shared__ int   s_dst[BATCH];
    __shared__ float s_w[BATCH];

    const int t     = threadIdx.x;
    const int lane  = t & 15;   // which float4 of the 64-dim row
    const int group = t >> 4;   // which edge within a pass

    const int base = blockIdx.x * BATCH;
    if (base >= E) return;
    const int n = (E - base < BATCH) ? (E - base) : BATCH;

    // ---- Stage batch of edges into smem (coalesced; int64 -> int32) ----
    if (t < n) {
        if (g_idx_is64) {
            const long long* p = (const long long*)edge_index;
            s_src[t] = (int)__ldg(p + base + t);
            s_dst[t] = (int)__ldg(p + E + base + t);
        } else {
            const int* p = (const int*)edge_index;
            s_src[t] = __ldg(p + base + t);
            s_dst[t] = __ldg(p + E + base + t);
        }
        s_w[t] = __ldg(w + base + t);
    }
    __syncthreads();

    // ---- Consume: each thread does PASSES edges, UNROLL gathers in flight ----
    #pragma unroll
    for (int p = 0; p < PASSES; p += UNROLL) {
        int    eidx[UNROLL];
        int    dsts[UNROLL];
        float  wts [UNROLL];
        float4 xv  [UNROLL];

        // Issue all gathers first (independent LDG.128s in flight)
        #pragma unroll
        for (int u = 0; u < UNROLL; u++) {
            int i = group + GROUPS * (p + u);
            eidx[u] = i;
            bool ok = (i < n);
            int  s  = ok ? s_src[i] : 0;
            dsts[u] = ok ? s_dst[i] : 0;
            wts [u] = ok ? s_w[i]   : 0.f;
            xv  [u] = __ldg(reinterpret_cast<const float4*>(
                          x + (long long)s * D + lane * 4));
        }
        // Then scale + fire-and-forget reductions
        #pragma unroll
        for (int u = 0; u < UNROLL; u++) {
            if (eidx[u] < n) {
                float wt = wts[u];
                float4 m;
                m.x = xv[u].x * wt; m.y = xv[u].y * wt;
                m.z = xv[u].z * wt; m.w = xv[u].w * wt;
                float* pdst = out + (long long)dsts[u] * D + lane * 4;
                asm volatile("red.global.add.v4.f32 [%0], {%1, %2, %3, %4};"
                             :: "l"(pdst), "f"(m.x), "f"(m.y), "f"(m.z), "f"(m.w)
                             : "memory");
            }
        }
    }
}

extern "C" void kernel_launch(void* const* d_in, const int* in_sizes, int n_in,
                              void* d_out, int out_size) {
    const float* x   = (const float*)d_in[0];
    const void*  ei  = d_in[1];
    const float* w   = (const float*)d_in[2];
    float*       out = (float*)d_out;

    const int E = in_sizes[1] / 2;   // edge_index is (2, E)

    // 1) zero output (poisoned 0xAA) + probe index dtype (block 0)
    {
        int n4 = out_size / 4;
        int blocks = (n4 + TPB - 1) / TPB;
        zero_and_probe_kernel<<<blocks, TPB>>>((float4*)out, n4,
                                               (const int*)ei, E);
    }

    // 2) batched gather-multiply-scatter
    {
        int blocks = (E + BATCH - 1) / BATCH;
        mp_scatter_batched_kernel<<<blocks, TPB>>>(x, ei, w, out, E);
    }
}